// round 3
// baseline (speedup 1.0000x reference)
#include <cuda_runtime.h>

#define NB   2
#define SEQ  2048
#define HID  1024
#define NHD  16
#define HDD  64

// Scratch (allocation-free rule: __device__ globals).
// NOTE: these are referenced ONLY from device code — passing a __device__
// symbol as a kernel arg from host code yields the host shadow address.
__device__ float g_Qch[NB * NHD * SEQ * 8];   // (b,h,s,8) tetra channels
__device__ float g_Kch[NB * NHD * SEQ * 8];
__device__ float g_V[NB * SEQ * HID];          // (b,s,H) row-major
__device__ float g_AttOut[NB * SEQ * HID];     // (b,s,H) row-major

// ---------------------------------------------------------------------------
// Kernel 1: tetra channels for Q and K.
// Only head-dim slots 0 and 2 of Q/K are ever used -> 64 dots per token.
// Each block handles 4 token rows; 8 warps x 8 dots each.
// ---------------------------------------------------------------------------
__global__ __launch_bounds__(256) void qk_channels_kernel(
    const float* __restrict__ x,
    const float* __restrict__ Wq, const float* __restrict__ Wk,
    const float* __restrict__ bq, const float* __restrict__ bk)
{
    __shared__ float xs[4][HID];
    __shared__ float tvals[4][64];

    const int tid = threadIdx.x;
    const int m0  = blockIdx.x * 4;   // first global token row (over B*S)

    for (int i = tid; i < 4 * (HID / 4); i += 256) {
        int r = i / (HID / 4);
        int c = (i % (HID / 4)) * 4;
        float4 v = *(const float4*)&x[(m0 + r) * HID + c];
        xs[r][c] = v.x; xs[r][c + 1] = v.y; xs[r][c + 2] = v.z; xs[r][c + 3] = v.w;
    }
    __syncthreads();

    const int warp = tid >> 5;
    const int lane = tid & 31;

    #pragma unroll
    for (int j = 0; j < 8; j++) {
        int d    = warp * 8 + j;         // dot index 0..63
        int qk   = d >> 5;               // 0 = Q, 1 = K
        int dd   = d & 31;
        int h    = dd >> 1;
        int slot = (dd & 1) * 2;         // 0 or 2
        const float* Wrow = (qk == 0 ? Wq : Wk) + (h * HDD + slot) * HID;

        float s0 = 0.f, s1 = 0.f, s2 = 0.f, s3 = 0.f;
        for (int k = lane; k < HID; k += 32) {
            float wv = Wrow[k];
            s0 += wv * xs[0][k];
            s1 += wv * xs[1][k];
            s2 += wv * xs[2][k];
            s3 += wv * xs[3][k];
        }
        #pragma unroll
        for (int off = 16; off; off >>= 1) {
            s0 += __shfl_down_sync(0xffffffffu, s0, off);
            s1 += __shfl_down_sync(0xffffffffu, s1, off);
            s2 += __shfl_down_sync(0xffffffffu, s2, off);
            s3 += __shfl_down_sync(0xffffffffu, s3, off);
        }
        if (lane == 0) {
            float bias = (qk == 0 ? bq : bk)[h * HDD + slot];
            tvals[0][d] = s0 + bias;
            tvals[1][d] = s1 + bias;
            tvals[2][d] = s2 + bias;
            tvals[3][d] = s3 + bias;
        }
    }
    __syncthreads();

    {
        int r  = tid >> 6;
        int d  = tid & 63;
        int m  = m0 + r;
        int b  = m / SEQ;
        int s  = m % SEQ;
        int qk = d >> 5;
        int dd = d & 31;
        int h  = dd >> 1;
        int which = dd & 1;

        float t  = tvals[r][d];
        float a  = 1.0f / (1.0f + expf(-t));
        float na = 1.0f - a;
        float nei = 1.0f - (a + na);
        nei = fminf(fmaxf(nei, 0.0f), 1.0f);

        float* dst = (qk == 0 ? g_Qch : g_Kch) + (((b * NHD + h) * SEQ + s) << 3) + which * 4;
        dst[0] = a; dst[1] = na; dst[2] = a * na; dst[3] = nei;
    }
}

// ---------------------------------------------------------------------------
// Kernel 2/4: C[M,N] = A[M,K] @ W[N,K]^T + bias.  128x128x8 tile, 8x8/thread.
// mode 0: A = Ain (harness input x), C = g_V   (device global)
// mode 1: A = g_AttOut (device global), C = Cout (harness d_out)
// ---------------------------------------------------------------------------
__global__ __launch_bounds__(256) void gemm_bias_kernel(
    const float* __restrict__ Ain, const float* __restrict__ W,
    const float* __restrict__ bias, float* __restrict__ Cout,
    int M, int N, int K, int mode)
{
    const float* A = (mode == 0) ? Ain  : (const float*)g_AttOut;
    float*       C = (mode == 0) ? g_V  : Cout;

    __shared__ float As[8][128];
    __shared__ float Ws[8][128];

    const int tid = threadIdx.x;
    const int bm  = blockIdx.y * 128;
    const int bn  = blockIdx.x * 128;
    const int tx  = tid & 15;
    const int ty  = tid >> 4;

    float acc[8][8] = {};

    const int lr = tid >> 1;
    const int lc = (tid & 1) * 4;
    const float* Aptr = A + (bm + lr) * K + lc;
    const float* Wptr = W + (bn + lr) * K + lc;

    for (int k0 = 0; k0 < K; k0 += 8) {
        float4 av = *(const float4*)(Aptr + k0);
        float4 wv = *(const float4*)(Wptr + k0);
        As[lc + 0][lr] = av.x; As[lc + 1][lr] = av.y;
        As[lc + 2][lr] = av.z; As[lc + 3][lr] = av.w;
        Ws[lc + 0][lr] = wv.x; Ws[lc + 1][lr] = wv.y;
        Ws[lc + 2][lr] = wv.z; Ws[lc + 3][lr] = wv.w;
        __syncthreads();

        #pragma unroll
        for (int kk = 0; kk < 8; kk++) {
            float am[8], wn[8];
            *(float4*)&am[0] = *(const float4*)&As[kk][ty * 8];
            *(float4*)&am[4] = *(const float4*)&As[kk][ty * 8 + 4];
            *(float4*)&wn[0] = *(const float4*)&Ws[kk][tx * 8];
            *(float4*)&wn[4] = *(const float4*)&Ws[kk][tx * 8 + 4];
            #pragma unroll
            for (int i = 0; i < 8; i++)
                #pragma unroll
                for (int j = 0; j < 8; j++)
                    acc[i][j] += am[i] * wn[j];
        }
        __syncthreads();
    }

    #pragma unroll
    for (int i = 0; i < 8; i++) {
        int row = bm + ty * 8 + i;
        #pragma unroll
        for (int j = 0; j < 8; j++) {
            int col = bn + tx * 8 + j;
            C[row * N + col] = acc[i][j] + bias[col];
        }
    }
}

// ---------------------------------------------------------------------------
// Kernel 3: fused rank-8 attention (reads/writes device globals directly).
// ---------------------------------------------------------------------------
#define BR 128
#define BT 128

__global__ __launch_bounds__(256) void attn_kernel()
{
    __shared__ float Ks[BT][8];
    __shared__ float Vs[BT][HDD];

    const int tid  = threadIdx.x;
    const int sblk = blockIdx.x;
    const int h    = blockIdx.y;
    const int b    = blockIdx.z;

    const int pr = tid & 127;    // row within block
    const int pg = tid >> 7;     // 0/1: column half
    const int c0 = pg * 32;

    const float* Qg = g_Qch + (((b * NHD + h) * SEQ + sblk * BR + pr) << 3);
    const float* Kg = g_Kch + (((size_t)(b * NHD + h) * SEQ) << 3);
    const float* Vg = g_V + (size_t)b * SEQ * HID + h * HDD;

    float q[8];
    {
        float4 q0 = *(const float4*)&Qg[0];
        float4 q1 = *(const float4*)&Qg[4];
        q[0] = q0.x; q[1] = q0.y; q[2] = q0.z; q[3] = q0.w;
        q[4] = q1.x; q[5] = q1.y; q[6] = q1.z; q[7] = q1.w;
    }

    float acc[32];
    #pragma unroll
    for (int j = 0; j < 32; j++) acc[j] = 0.0f;
    float z = 0.0f;

    for (int t0 = 0; t0 < SEQ; t0 += BT) {
        __syncthreads();
        for (int i = tid; i < BT * 8; i += 256)
            Ks[i >> 3][i & 7] = Kg[(t0 << 3) + i];
        for (int i = tid; i < BT * HDD; i += 256)
            Vs[i >> 6][i & 63] = Vg[(size_t)(t0 + (i >> 6)) * HID + (i & 63)];
        __syncthreads();

        #pragma unroll 4
        for (int t = 0; t < BT; t++) {
            float4 k0 = *(const float4*)&Ks[t][0];
            float4 k1 = *(const float4*)&Ks[t][4];
            float sa = q[0] * k0.x + q[1] * k0.y + q[2] * k0.z + q[3] * k0.w;
            float sb = q[4] * k1.x + q[5] * k1.y + q[6] * k1.z + q[7] * k1.w;
            float xv = sa * 0.125f + sb * 0.1f;   // score in [0, ~0.47]
            // exp(x) ~ degree-5 Taylor, rel err < 1.5e-5 on [0, 0.6]
            float e = 1.0f + xv * (1.0f + xv * (0.5f + xv * (0.16666667f
                      + xv * (0.041666667f + xv * 0.0083333333f))));
            z += e;
            const float4* vrow = (const float4*)&Vs[t][c0];
            #pragma unroll
            for (int j4 = 0; j4 < 8; j4++) {
                float4 v = vrow[j4];
                acc[j4 * 4 + 0] += e * v.x;
                acc[j4 * 4 + 1] += e * v.y;
                acc[j4 * 4 + 2] += e * v.z;
                acc[j4 * 4 + 3] += e * v.w;
            }
        }
    }

    const float inv = 1.0f / z;
    float* Og = g_AttOut + (size_t)(b * SEQ + sblk * BR + pr) * HID + h * HDD + c0;
    #pragma unroll
    for (int j4 = 0; j4 < 8; j4++) {
        float4 v;
        v.x = acc[j4 * 4 + 0] * inv;
        v.y = acc[j4 * 4 + 1] * inv;
        v.z = acc[j4 * 4 + 2] * inv;
        v.w = acc[j4 * 4 + 3] * inv;
        *(float4*)&Og[j4 * 4] = v;
    }
}

// ---------------------------------------------------------------------------
extern "C" void kernel_launch(void* const* d_in, const int* in_sizes, int n_in,
                              void* d_out, int out_size)
{
    // Identify inputs by element count (robust to metadata ordering):
    //   x: B*S*H = 4194304, weights: 1048576 (order q,k,v,o), biases: 1024
    const float* x = nullptr;
    const float* Wm[4] = {nullptr, nullptr, nullptr, nullptr};
    const float* bm[4] = {nullptr, nullptr, nullptr, nullptr};
    int wi = 0, bi = 0;
    for (int i = 0; i < n_in; i++) {
        if (in_sizes[i] == NB * SEQ * HID)      x = (const float*)d_in[i];
        else if (in_sizes[i] == HID * HID) { if (wi < 4) Wm[wi++] = (const float*)d_in[i]; }
        else if (in_sizes[i] == HID)       { if (bi < 4) bm[bi++] = (const float*)d_in[i]; }
    }
    const float* Wq = Wm[0]; const float* Wk = Wm[1];
    const float* Wv = Wm[2]; const float* Wo = Wm[3];
    const float* bq = bm[0]; const float* bk = bm[1];
    const float* bv = bm[2]; const float* bo = bm[3];
    float* out = (float*)d_out;

    const int M = NB * SEQ;  // 4096

    // 1. tetra channels for Q, K
    qk_channels_kernel<<<M / 4, 256>>>(x, Wq, Wk, bq, bk);

    // 2. V projection: g_V = x @ Wv^T + bv  (mode 0 -> writes g_V internally)
    {
        dim3 grid(HID / 128, M / 128);
        gemm_bias_kernel<<<grid, 256>>>(x, Wv, bv, nullptr, M, HID, HID, 0);
    }

    // 3. fused attention -> g_AttOut (B,S,H)
    {
        dim3 grid(SEQ / BR, NHD, NB);
        attn_kernel<<<grid, 256>>>();
    }

    // 4. output projection: out = g_AttOut @ Wo^T + bo  (mode 1 -> reads g_AttOut)
    {
        dim3 grid(HID / 128, M / 128);
        gemm_bias_kernel<<<grid, 256>>>(nullptr, Wo, bo, out, M, HID, HID, 1);
    }
}

// round 5
// speedup vs baseline: 1.6285x; 1.6285x over previous
#include <cuda_runtime.h>
#include <cstdint>

#define NB   2
#define SEQ  2048
#define HID  1024
#define NHD  16
#define HDD  64

// Scratch (allocation-free rule). Referenced ONLY from device code.
__device__ float g_Qch[NB * NHD * SEQ * 8];
__device__ float g_Kch[NB * NHD * SEQ * 8];
__device__ float g_V[NB * SEQ * HID];
__device__ float g_AttOut[NB * SEQ * HID];

// ---------------------------------------------------------------------------
// mma.sync tf32 helpers (compute_103-safe: Ampere-era instructions only)
// ---------------------------------------------------------------------------
__device__ __forceinline__ float to_tf32(float x) {
    float y;
    asm("cvt.rna.tf32.f32 %0, %1;" : "=f"(y) : "f"(x));
    return y;
}
__device__ __forceinline__ void mma_tf32(float* d, const uint32_t* a, const uint32_t* b) {
    asm volatile(
        "mma.sync.aligned.m16n8k8.row.col.f32.tf32.tf32.f32 "
        "{%0,%1,%2,%3}, {%4,%5,%6,%7}, {%8,%9}, {%0,%1,%2,%3};"
        : "+f"(d[0]), "+f"(d[1]), "+f"(d[2]), "+f"(d[3])
        : "r"(a[0]), "r"(a[1]), "r"(a[2]), "r"(a[3]), "r"(b[0]), "r"(b[1]));
}

// ---------------------------------------------------------------------------
// Kernel 1: tetra channels for Q and K (only head-dim slots 0/2 are used).
// ---------------------------------------------------------------------------
__global__ __launch_bounds__(256) void qk_channels_kernel(
    const float* __restrict__ x,
    const float* __restrict__ Wq, const float* __restrict__ Wk,
    const float* __restrict__ bq, const float* __restrict__ bk)
{
    __shared__ float xs[4][HID];
    __shared__ float tvals[4][64];

    const int tid = threadIdx.x;
    const int m0  = blockIdx.x * 4;

    for (int i = tid; i < 4 * (HID / 4); i += 256) {
        int r = i / (HID / 4);
        int c = (i % (HID / 4)) * 4;
        float4 v = *(const float4*)&x[(m0 + r) * HID + c];
        xs[r][c] = v.x; xs[r][c + 1] = v.y; xs[r][c + 2] = v.z; xs[r][c + 3] = v.w;
    }
    __syncthreads();

    const int warp = tid >> 5;
    const int lane = tid & 31;

    #pragma unroll
    for (int j = 0; j < 8; j++) {
        int d    = warp * 8 + j;
        int qk   = d >> 5;
        int dd   = d & 31;
        int h    = dd >> 1;
        int slot = (dd & 1) * 2;
        const float* Wrow = (qk == 0 ? Wq : Wk) + (h * HDD + slot) * HID;

        float s0 = 0.f, s1 = 0.f, s2 = 0.f, s3 = 0.f;
        for (int k = lane; k < HID; k += 32) {
            float wv = Wrow[k];
            s0 += wv * xs[0][k];
            s1 += wv * xs[1][k];
            s2 += wv * xs[2][k];
            s3 += wv * xs[3][k];
        }
        #pragma unroll
        for (int off = 16; off; off >>= 1) {
            s0 += __shfl_down_sync(0xffffffffu, s0, off);
            s1 += __shfl_down_sync(0xffffffffu, s1, off);
            s2 += __shfl_down_sync(0xffffffffu, s2, off);
            s3 += __shfl_down_sync(0xffffffffu, s3, off);
        }
        if (lane == 0) {
            float bias = (qk == 0 ? bq : bk)[h * HDD + slot];
            tvals[0][d] = s0 + bias;
            tvals[1][d] = s1 + bias;
            tvals[2][d] = s2 + bias;
            tvals[3][d] = s3 + bias;
        }
    }
    __syncthreads();

    {
        int r  = tid >> 6;
        int d  = tid & 63;
        int m  = m0 + r;
        int b  = m / SEQ;
        int s  = m % SEQ;
        int qk = d >> 5;
        int dd = d & 31;
        int h  = dd >> 1;
        int which = dd & 1;

        float t  = tvals[r][d];
        float a  = 1.0f / (1.0f + expf(-t));
        float na = 1.0f - a;
        float nei = fminf(fmaxf(1.0f - (a + na), 0.0f), 1.0f);

        float4 v; v.x = a; v.y = na; v.z = a * na; v.w = nei;
        float* dst = (qk == 0 ? g_Qch : g_Kch) + (((b * NHD + h) * SEQ + s) << 3) + which * 4;
        *(float4*)dst = v;
    }
}

// ---------------------------------------------------------------------------
// Kernel 2/4: mma.sync tf32 GEMM.  C[4096,1024] = A @ W^T + bias.
// Block tile 128x128, 8 warps as 2(m) x 4(n), warp tile 64x32 via m16n8k8.
// Smem tiles 128x32 with stride 36 (conflict-free fragment reads).
// mode 0: A = Ain (input x), C = g_V.   mode 1: A = g_AttOut, C = Cout.
// ---------------------------------------------------------------------------
__global__ __launch_bounds__(256) void gemm_mma_kernel(
    const float* __restrict__ Ain, const float* __restrict__ W,
    const float* __restrict__ bias, float* __restrict__ Cout, int mode)
{
    const float* A = (mode == 0) ? Ain : (const float*)g_AttOut;
    float*       C = (mode == 0) ? g_V : Cout;

    __shared__ float As[128][36];
    __shared__ float Bs[128][36];

    const int tid  = threadIdx.x;
    const int lane = tid & 31;
    const int wid  = tid >> 5;
    const int bm   = blockIdx.y * 128;
    const int bn   = blockIdx.x * 128;
    const int wm   = (wid & 1) * 64;      // warp m offset in tile
    const int wn   = (wid >> 1) * 32;     // warp n offset in tile
    const int gid  = lane >> 2;           // 0..7
    const int tig  = lane & 3;            // 0..3

    float c[4][4][4];
    #pragma unroll
    for (int mt = 0; mt < 4; mt++)
        #pragma unroll
        for (int nt = 0; nt < 4; nt++)
            #pragma unroll
            for (int k = 0; k < 4; k++) c[mt][nt][k] = 0.0f;

    for (int kc = 0; kc < HID; kc += 32) {
        __syncthreads();
        // stage 128x32 tiles of A and W, rounded to tf32
        #pragma unroll
        for (int i = 0; i < 4; i++) {
            int idx  = tid + i * 256;     // float4 id 0..1023
            int row  = idx >> 3;
            int col4 = (idx & 7) * 4;
            float4 va = *(const float4*)&A[(size_t)(bm + row) * HID + kc + col4];
            float4 vb = *(const float4*)&W[(size_t)(bn + row) * HID + kc + col4];
            As[row][col4 + 0] = to_tf32(va.x); As[row][col4 + 1] = to_tf32(va.y);
            As[row][col4 + 2] = to_tf32(va.z); As[row][col4 + 3] = to_tf32(va.w);
            Bs[row][col4 + 0] = to_tf32(vb.x); Bs[row][col4 + 1] = to_tf32(vb.y);
            Bs[row][col4 + 2] = to_tf32(vb.z); Bs[row][col4 + 3] = to_tf32(vb.w);
        }
        __syncthreads();

        #pragma unroll
        for (int ks = 0; ks < 32; ks += 8) {
            uint32_t af[4][4];
            #pragma unroll
            for (int mt = 0; mt < 4; mt++) {
                int r0 = wm + mt * 16 + gid;
                af[mt][0] = __float_as_uint(As[r0][ks + tig]);
                af[mt][1] = __float_as_uint(As[r0 + 8][ks + tig]);
                af[mt][2] = __float_as_uint(As[r0][ks + tig + 4]);
                af[mt][3] = __float_as_uint(As[r0 + 8][ks + tig + 4]);
            }
            uint32_t bf[4][2];
            #pragma unroll
            for (int nt = 0; nt < 4; nt++) {
                int n0 = wn + nt * 8 + gid;
                bf[nt][0] = __float_as_uint(Bs[n0][ks + tig]);
                bf[nt][1] = __float_as_uint(Bs[n0][ks + tig + 4]);
            }
            #pragma unroll
            for (int mt = 0; mt < 4; mt++)
                #pragma unroll
                for (int nt = 0; nt < 4; nt++)
                    mma_tf32(c[mt][nt], af[mt], bf[nt]);
        }
    }

    // epilogue: bias + store (float2 per c-pair)
    #pragma unroll
    for (int mt = 0; mt < 4; mt++) {
        int row0 = bm + wm + mt * 16 + gid;
        #pragma unroll
        for (int nt = 0; nt < 4; nt++) {
            int col0 = bn + wn + nt * 8 + 2 * tig;
            float b0 = bias[col0], b1 = bias[col0 + 1];
            float2 v0; v0.x = c[mt][nt][0] + b0; v0.y = c[mt][nt][1] + b1;
            float2 v1; v1.x = c[mt][nt][2] + b0; v1.y = c[mt][nt][3] + b1;
            *(float2*)&C[(size_t)row0 * HID + col0] = v0;
            *(float2*)&C[(size_t)(row0 + 8) * HID + col0] = v1;
        }
    }
}

// ---------------------------------------------------------------------------
// Kernel 3: fused rank-8 attention. One thread = one q-row, all 64 cols.
// exp via degree-5 poly (scores in [0, ~0.47] -> no max subtraction needed).
// ---------------------------------------------------------------------------
#define BR 256
#define BT 128

__global__ __launch_bounds__(256) void attn_kernel()
{
    __shared__ float Ks[BT][8];
    __shared__ float Vs[BT][HDD];

    const int tid  = threadIdx.x;
    const int sblk = blockIdx.x;
    const int h    = blockIdx.y;
    const int b    = blockIdx.z;

    const float* Qg = g_Qch + (((b * NHD + h) * SEQ + sblk * BR + tid) << 3);
    const float* Kg = g_Kch + (((size_t)(b * NHD + h) * SEQ) << 3);
    const float* Vg = g_V + (size_t)b * SEQ * HID + h * HDD;

    float q[8];
    {
        float4 q0 = *(const float4*)&Qg[0];
        float4 q1 = *(const float4*)&Qg[4];
        q[0] = q0.x; q[1] = q0.y; q[2] = q0.z; q[3] = q0.w;
        q[4] = q1.x; q[5] = q1.y; q[6] = q1.z; q[7] = q1.w;
    }

    float acc[64];
    #pragma unroll
    for (int j = 0; j < 64; j++) acc[j] = 0.0f;
    float z = 0.0f;

    for (int t0 = 0; t0 < SEQ; t0 += BT) {
        __syncthreads();
        ((float4*)Ks)[tid] = ((const float4*)(Kg + ((size_t)t0 << 3)))[tid];
        #pragma unroll
        for (int i = 0; i < 8; i++) {
            int idx = tid + i * 256;
            int row = idx >> 4;
            int col = (idx & 15) * 4;
            *(float4*)&Vs[row][col] = *(const float4*)&Vg[(size_t)(t0 + row) * HID + col];
        }
        __syncthreads();

        #pragma unroll 1
        for (int t = 0; t < BT; t++) {
            float4 k0 = *(const float4*)&Ks[t][0];
            float4 k1 = *(const float4*)&Ks[t][4];
            float sa = q[0] * k0.x + q[1] * k0.y + q[2] * k0.z + q[3] * k0.w;
            float sb = q[4] * k1.x + q[5] * k1.y + q[6] * k1.z + q[7] * k1.w;
            float xv = sa * 0.125f + sb * 0.1f;
            float e = 1.0f + xv * (1.0f + xv * (0.5f + xv * (0.16666667f
                      + xv * (0.041666667f + xv * 0.0083333333f))));
            z += e;
            #pragma unroll
            for (int j4 = 0; j4 < 16; j4++) {
                float4 v = *(const float4*)&Vs[t][j4 * 4];   // broadcast
                acc[j4 * 4 + 0] += e * v.x;
                acc[j4 * 4 + 1] += e * v.y;
                acc[j4 * 4 + 2] += e * v.z;
                acc[j4 * 4 + 3] += e * v.w;
            }
        }
    }

    const float inv = 1.0f / z;
    float* Og = g_AttOut + (size_t)(b * SEQ + sblk * BR + tid) * HID + h * HDD;
    #pragma unroll
    for (int j4 = 0; j4 < 16; j4++) {
        float4 v;
        v.x = acc[j4 * 4 + 0] * inv;
        v.y = acc[j4 * 4 + 1] * inv;
        v.z = acc[j4 * 4 + 2] * inv;
        v.w = acc[j4 * 4 + 3] * inv;
        *(float4*)&Og[j4 * 4] = v;
    }
}

// ---------------------------------------------------------------------------
extern "C" void kernel_launch(void* const* d_in, const int* in_sizes, int n_in,
                              void* d_out, int out_size)
{
    const float* x = nullptr;
    const float* Wm[4] = {nullptr, nullptr, nullptr, nullptr};
    const float* bm[4] = {nullptr, nullptr, nullptr, nullptr};
    int wi = 0, bi = 0;
    for (int i = 0; i < n_in; i++) {
        if (in_sizes[i] == NB * SEQ * HID)      x = (const float*)d_in[i];
        else if (in_sizes[i] == HID * HID) { if (wi < 4) Wm[wi++] = (const float*)d_in[i]; }
        else if (in_sizes[i] == HID)       { if (bi < 4) bm[bi++] = (const float*)d_in[i]; }
    }
    const float* Wq = Wm[0]; const float* Wk = Wm[1];
    const float* Wv = Wm[2]; const float* Wo = Wm[3];
    const float* bq = bm[0]; const float* bk = bm[1];
    const float* bv = bm[2]; const float* bo = bm[3];
    float* out = (float*)d_out;

    const int M = NB * SEQ;  // 4096

    // 1. tetra channels for Q, K
    qk_channels_kernel<<<M / 4, 256>>>(x, Wq, Wk, bq, bk);

    // 2. V projection (mma.sync tf32): g_V = x @ Wv^T + bv
    {
        dim3 grid(HID / 128, M / 128);
        gemm_mma_kernel<<<grid, 256>>>(x, Wv, bv, nullptr, 0);
    }

    // 3. fused attention -> g_AttOut
    {
        dim3 grid(SEQ / BR, NHD, NB);
        attn_kernel<<<grid, 256>>>();
    }

    // 4. output projection (mma.sync tf32): out = g_AttOut @ Wo^T + bo
    {
        dim3 grid(HID / 128, M / 128);
        gemm_mma_kernel<<<grid, 256>>>(nullptr, Wo, bo, out, 1);
    }
}

// round 6
// speedup vs baseline: 3.7171x; 2.2826x over previous
#include <cuda_runtime.h>
#include <cstdint>

#define NB   2
#define SEQ  2048
#define HID  1024
#define NHD  16
#define HDD  64

// Scratch (allocation-free rule). Referenced ONLY from device code.
__device__ float g_Qch[NB * NHD * SEQ * 8];   // tetra channels, score scales FOLDED IN
__device__ float g_Kch[NB * NHD * SEQ * 8];
__device__ float g_V[NB * SEQ * HID];
__device__ float g_AttOut[NB * SEQ * HID];

// ---------------------------------------------------------------------------
// mma.sync tf32 helpers (compute_103-safe)
// ---------------------------------------------------------------------------
__device__ __forceinline__ float to_tf32(float x) {
    float y;
    asm("cvt.rna.tf32.f32 %0, %1;" : "=f"(y) : "f"(x));
    return y;
}
__device__ __forceinline__ void mma_tf32(float* d, const uint32_t* a, const uint32_t* b) {
    asm volatile(
        "mma.sync.aligned.m16n8k8.row.col.f32.tf32.tf32.f32 "
        "{%0,%1,%2,%3}, {%4,%5,%6,%7}, {%8,%9}, {%0,%1,%2,%3};"
        : "+f"(d[0]), "+f"(d[1]), "+f"(d[2]), "+f"(d[3])
        : "r"(a[0]), "r"(a[1]), "r"(a[2]), "r"(a[3]), "r"(b[0]), "r"(b[1]));
}
// exp(x), x in [0, ~0.5]: degree-5 Taylor, rel err < 1.5e-5
__device__ __forceinline__ float exp_pos(float x) {
    return 1.0f + x * (1.0f + x * (0.5f + x * (0.16666667f
           + x * (0.041666667f + x * 0.0083333333f))));
}

// ---------------------------------------------------------------------------
// Kernel 1: tetra channels for Q and K (only head-dim slots 0/2 are used).
// Score scales folded into Q channels: slot0 x 1/8, slot2 x 0.1.
// Channels pre-rounded to tf32 (they feed mma.sync directly).
// ---------------------------------------------------------------------------
__global__ __launch_bounds__(256) void qk_channels_kernel(
    const float* __restrict__ x,
    const float* __restrict__ Wq, const float* __restrict__ Wk,
    const float* __restrict__ bq, const float* __restrict__ bk)
{
    __shared__ float xs[4][HID];
    __shared__ float tvals[4][64];

    const int tid = threadIdx.x;
    const int m0  = blockIdx.x * 4;

    for (int i = tid; i < 4 * (HID / 4); i += 256) {
        int r = i / (HID / 4);
        int c = (i % (HID / 4)) * 4;
        float4 v = *(const float4*)&x[(m0 + r) * HID + c];
        xs[r][c] = v.x; xs[r][c + 1] = v.y; xs[r][c + 2] = v.z; xs[r][c + 3] = v.w;
    }
    __syncthreads();

    const int warp = tid >> 5;
    const int lane = tid & 31;

    #pragma unroll
    for (int j = 0; j < 8; j++) {
        int d    = warp * 8 + j;
        int qk   = d >> 5;
        int dd   = d & 31;
        int h    = dd >> 1;
        int slot = (dd & 1) * 2;
        const float* Wrow = (qk == 0 ? Wq : Wk) + (h * HDD + slot) * HID;

        float s0 = 0.f, s1 = 0.f, s2 = 0.f, s3 = 0.f;
        for (int k = lane; k < HID; k += 32) {
            float wv = Wrow[k];
            s0 += wv * xs[0][k];
            s1 += wv * xs[1][k];
            s2 += wv * xs[2][k];
            s3 += wv * xs[3][k];
        }
        #pragma unroll
        for (int off = 16; off; off >>= 1) {
            s0 += __shfl_down_sync(0xffffffffu, s0, off);
            s1 += __shfl_down_sync(0xffffffffu, s1, off);
            s2 += __shfl_down_sync(0xffffffffu, s2, off);
            s3 += __shfl_down_sync(0xffffffffu, s3, off);
        }
        if (lane == 0) {
            float bias = (qk == 0 ? bq : bk)[h * HDD + slot];
            tvals[0][d] = s0 + bias;
            tvals[1][d] = s1 + bias;
            tvals[2][d] = s2 + bias;
            tvals[3][d] = s3 + bias;
        }
    }
    __syncthreads();

    {
        int r  = tid >> 6;
        int d  = tid & 63;
        int m  = m0 + r;
        int b  = m / SEQ;
        int s  = m % SEQ;
        int qk = d >> 5;
        int dd = d & 31;
        int h  = dd >> 1;
        int which = dd & 1;

        float t  = tvals[r][d];
        float a  = 1.0f / (1.0f + expf(-t));
        float na = 1.0f - a;
        float nei = fminf(fmaxf(1.0f - (a + na), 0.0f), 1.0f);

        // fold score scale into Q channels (1/sqrt(HD)=0.125 for slot0, 0.1 for slot2)
        float sc = (qk == 0) ? ((which == 0) ? 0.125f : 0.1f) : 1.0f;
        float4 v;
        v.x = to_tf32(a * sc);
        v.y = to_tf32(na * sc);
        v.z = to_tf32(a * na * sc);
        v.w = to_tf32(nei * sc);
        float* dst = (qk == 0 ? g_Qch : g_Kch) + (((b * NHD + h) * SEQ + s) << 3) + which * 4;
        *(float4*)dst = v;
    }
}

// ---------------------------------------------------------------------------
// Kernel 2/4: mma.sync tf32 GEMM.  C[4096,1024] = A @ W^T + bias.
// ---------------------------------------------------------------------------
__global__ __launch_bounds__(256) void gemm_mma_kernel(
    const float* __restrict__ Ain, const float* __restrict__ W,
    const float* __restrict__ bias, float* __restrict__ Cout, int mode)
{
    const float* A = (mode == 0) ? Ain : (const float*)g_AttOut;
    float*       C = (mode == 0) ? g_V : Cout;

    __shared__ float As[128][36];
    __shared__ float Bs[128][36];

    const int tid  = threadIdx.x;
    const int lane = tid & 31;
    const int wid  = tid >> 5;
    const int bm   = blockIdx.y * 128;
    const int bn   = blockIdx.x * 128;
    const int wm   = (wid & 1) * 64;
    const int wn   = (wid >> 1) * 32;
    const int gid  = lane >> 2;
    const int tig  = lane & 3;

    float c[4][4][4];
    #pragma unroll
    for (int mt = 0; mt < 4; mt++)
        #pragma unroll
        for (int nt = 0; nt < 4; nt++)
            #pragma unroll
            for (int k = 0; k < 4; k++) c[mt][nt][k] = 0.0f;

    for (int kc = 0; kc < HID; kc += 32) {
        __syncthreads();
        #pragma unroll
        for (int i = 0; i < 4; i++) {
            int idx  = tid + i * 256;
            int row  = idx >> 3;
            int col4 = (idx & 7) * 4;
            float4 va = *(const float4*)&A[(size_t)(bm + row) * HID + kc + col4];
            float4 vb = *(const float4*)&W[(size_t)(bn + row) * HID + kc + col4];
            As[row][col4 + 0] = to_tf32(va.x); As[row][col4 + 1] = to_tf32(va.y);
            As[row][col4 + 2] = to_tf32(va.z); As[row][col4 + 3] = to_tf32(va.w);
            Bs[row][col4 + 0] = to_tf32(vb.x); Bs[row][col4 + 1] = to_tf32(vb.y);
            Bs[row][col4 + 2] = to_tf32(vb.z); Bs[row][col4 + 3] = to_tf32(vb.w);
        }
        __syncthreads();

        #pragma unroll
        for (int ks = 0; ks < 32; ks += 8) {
            uint32_t af[4][4];
            #pragma unroll
            for (int mt = 0; mt < 4; mt++) {
                int r0 = wm + mt * 16 + gid;
                af[mt][0] = __float_as_uint(As[r0][ks + tig]);
                af[mt][1] = __float_as_uint(As[r0 + 8][ks + tig]);
                af[mt][2] = __float_as_uint(As[r0][ks + tig + 4]);
                af[mt][3] = __float_as_uint(As[r0 + 8][ks + tig + 4]);
            }
            uint32_t bf[4][2];
            #pragma unroll
            for (int nt = 0; nt < 4; nt++) {
                int n0 = wn + nt * 8 + gid;
                bf[nt][0] = __float_as_uint(Bs[n0][ks + tig]);
                bf[nt][1] = __float_as_uint(Bs[n0][ks + tig + 4]);
            }
            #pragma unroll
            for (int mt = 0; mt < 4; mt++)
                #pragma unroll
                for (int nt = 0; nt < 4; nt++)
                    mma_tf32(c[mt][nt], af[mt], bf[nt]);
        }
    }

    #pragma unroll
    for (int mt = 0; mt < 4; mt++) {
        int row0 = bm + wm + mt * 16 + gid;
        #pragma unroll
        for (int nt = 0; nt < 4; nt++) {
            int col0 = bn + wn + nt * 8 + 2 * tig;
            float b0 = bias[col0], b1 = bias[col0 + 1];
            float2 v0; v0.x = c[mt][nt][0] + b0; v0.y = c[mt][nt][1] + b1;
            float2 v1; v1.x = c[mt][nt][2] + b0; v1.y = c[mt][nt][3] + b1;
            *(float2*)&C[(size_t)row0 * HID + col0] = v0;
            *(float2*)&C[(size_t)(row0 + 8) * HID + col0] = v1;
        }
    }
}

// ---------------------------------------------------------------------------
// Kernel 3: tensor-core attention.
// Block = (b, h, 64 q-rows); iterates 64-key tiles.
// S-tile (64x64) = ONE m16n8k8 tf32 MMA per 16x8 tile (rank-8 trick, K=8).
// exp applied in registers, P routed via smem (tf32) to re-fragment for P.V.
// Z accumulated per-thread, reduced once at the end.
// S-phase warp layout: 2(m) x 4(n), warp tile 32x16.
// O-phase warp layout: 4(m) x 2(n), warp tile 16x32.
// ---------------------------------------------------------------------------
#define BQ 64
#define BK 64

__global__ __launch_bounds__(256) void attn_mma_kernel()
{
    __shared__ float Qs[BQ][12];   // stride 12: (12*gid+tig)%32 all distinct
    __shared__ float Ks[BK][12];
    __shared__ float Ps[BQ][68];   // stride 68: (4*gid+tig)%32 all distinct
    __shared__ float Vs[BK][72];   // stride 72: (8*tig+gid)%32 all distinct
    __shared__ float z_s[BQ];

    const int tid  = threadIdx.x;
    const int lane = tid & 31;
    const int wid  = tid >> 5;
    const int gid  = lane >> 2;
    const int tig  = lane & 3;
    const int q0   = blockIdx.x * BQ;
    const int h    = blockIdx.y;
    const int b    = blockIdx.z;

    const int wmS = (wid & 1) * 32;   // S-phase m offset
    const int wnS = (wid >> 1) * 16;  // S-phase n offset
    const int wmO = (wid & 3) * 16;   // O-phase m offset
    const int wnO = (wid >> 2) * 32;  // O-phase n offset

    const float* Qg = g_Qch + (((size_t)(b * NHD + h) * SEQ + q0) << 3);
    const float* Kg = g_Kch + (((size_t)(b * NHD + h) * SEQ) << 3);
    const float* Vg = g_V + (size_t)b * SEQ * HID + h * HDD;

    // stage Q tile (64 rows x 8 ch)
    if (tid < 128) {
        int r = tid >> 1, c4 = (tid & 1) * 4;
        float4 v = *(const float4*)&Qg[r * 8 + c4];
        Qs[r][c4 + 0] = v.x; Qs[r][c4 + 1] = v.y; Qs[r][c4 + 2] = v.z; Qs[r][c4 + 3] = v.w;
    }
    __syncthreads();

    // Q A-fragments (fixed for whole kernel)
    uint32_t aq[2][4];
    #pragma unroll
    for (int mt = 0; mt < 2; mt++) {
        int r0 = wmS + mt * 16 + gid;
        aq[mt][0] = __float_as_uint(Qs[r0][tig]);
        aq[mt][1] = __float_as_uint(Qs[r0 + 8][tig]);
        aq[mt][2] = __float_as_uint(Qs[r0][tig + 4]);
        aq[mt][3] = __float_as_uint(Qs[r0 + 8][tig + 4]);
    }

    float o[4][4];
    #pragma unroll
    for (int nt = 0; nt < 4; nt++)
        #pragma unroll
        for (int k = 0; k < 4; k++) o[nt][k] = 0.0f;
    float zacc[2][2] = {{0.f, 0.f}, {0.f, 0.f}};

    for (int kt = 0; kt < SEQ; kt += BK) {
        __syncthreads();   // prev O-phase done with Ks/Vs
        // stage K channels (64 x 8)
        if (tid < 128) {
            int r = tid >> 1, c4 = (tid & 1) * 4;
            float4 v = *(const float4*)&Kg[((size_t)(kt)) * 8 + r * 8 + c4];
            Ks[r][c4 + 0] = v.x; Ks[r][c4 + 1] = v.y; Ks[r][c4 + 2] = v.z; Ks[r][c4 + 3] = v.w;
        }
        // stage V tile (64 x 64), tf32-rounded
        #pragma unroll
        for (int i = 0; i < 4; i++) {
            int idx = tid + i * 256;
            int t   = idx >> 4;
            int d4  = (idx & 15) * 4;
            float4 v = *(const float4*)&Vg[(size_t)(kt + t) * HID + d4];
            Vs[t][d4 + 0] = to_tf32(v.x); Vs[t][d4 + 1] = to_tf32(v.y);
            Vs[t][d4 + 2] = to_tf32(v.z); Vs[t][d4 + 3] = to_tf32(v.w);
        }
        __syncthreads();

        // ---- S phase: 4 MMAs (K=8 = full rank) ----
        uint32_t bk_[2][2];
        #pragma unroll
        for (int nt = 0; nt < 2; nt++) {
            int n0 = wnS + nt * 8 + gid;
            bk_[nt][0] = __float_as_uint(Ks[n0][tig]);
            bk_[nt][1] = __float_as_uint(Ks[n0][tig + 4]);
        }
        float c[2][2][4];
        #pragma unroll
        for (int mt = 0; mt < 2; mt++)
            #pragma unroll
            for (int nt = 0; nt < 2; nt++) {
                #pragma unroll
                for (int k = 0; k < 4; k++) c[mt][nt][k] = 0.0f;
                mma_tf32(c[mt][nt], aq[mt], bk_[nt]);
            }

        // exp + store P (tf32) to smem, accumulate z
        #pragma unroll
        for (int mt = 0; mt < 2; mt++) {
            int r = wmS + mt * 16 + gid;
            #pragma unroll
            for (int nt = 0; nt < 2; nt++) {
                int cc = wnS + nt * 8 + 2 * tig;
                float e0 = exp_pos(c[mt][nt][0]);
                float e1 = exp_pos(c[mt][nt][1]);
                float e2 = exp_pos(c[mt][nt][2]);
                float e3 = exp_pos(c[mt][nt][3]);
                zacc[mt][0] += e0 + e1;
                zacc[mt][1] += e2 + e3;
                Ps[r][cc]     = to_tf32(e0);
                Ps[r][cc + 1] = to_tf32(e1);
                Ps[r + 8][cc]     = to_tf32(e2);
                Ps[r + 8][cc + 1] = to_tf32(e3);
            }
        }
        __syncthreads();

        // ---- O phase: P(64xBK) @ V(BKx64), 8 k-steps x 4 n-tiles ----
        #pragma unroll
        for (int k8 = 0; k8 < BK; k8 += 8) {
            uint32_t ap[4];
            ap[0] = __float_as_uint(Ps[wmO + gid][k8 + tig]);
            ap[1] = __float_as_uint(Ps[wmO + gid + 8][k8 + tig]);
            ap[2] = __float_as_uint(Ps[wmO + gid][k8 + tig + 4]);
            ap[3] = __float_as_uint(Ps[wmO + gid + 8][k8 + tig + 4]);
            #pragma unroll
            for (int nt = 0; nt < 4; nt++) {
                int n0 = wnO + nt * 8 + gid;
                uint32_t bv[2];
                bv[0] = __float_as_uint(Vs[k8 + tig][n0]);
                bv[1] = __float_as_uint(Vs[k8 + tig + 4][n0]);
                mma_tf32(o[nt], ap, bv);
            }
        }
    }

    // ---- Z reduction ----
    __syncthreads();
    if (tid < BQ) z_s[tid] = 0.0f;
    __syncthreads();
    #pragma unroll
    for (int mt = 0; mt < 2; mt++)
        #pragma unroll
        for (int hf = 0; hf < 2; hf++) {
            float zv = zacc[mt][hf];
            zv += __shfl_xor_sync(0xffffffffu, zv, 1);
            zv += __shfl_xor_sync(0xffffffffu, zv, 2);
            if (tig == 0)
                atomicAdd(&z_s[wmS + mt * 16 + hf * 8 + gid], zv);
        }
    __syncthreads();

    // ---- normalize + store ----
    const float inv0 = 1.0f / z_s[wmO + gid];
    const float inv1 = 1.0f / z_s[wmO + gid + 8];
    float* Og = g_AttOut + (size_t)(b * SEQ + q0) * HID + h * HDD;
    #pragma unroll
    for (int nt = 0; nt < 4; nt++) {
        int cc = wnO + nt * 8 + 2 * tig;
        float2 v0; v0.x = o[nt][0] * inv0; v0.y = o[nt][1] * inv0;
        float2 v1; v1.x = o[nt][2] * inv1; v1.y = o[nt][3] * inv1;
        *(float2*)&Og[(size_t)(wmO + gid) * HID + cc] = v0;
        *(float2*)&Og[(size_t)(wmO + gid + 8) * HID + cc] = v1;
    }
}

// ---------------------------------------------------------------------------
extern "C" void kernel_launch(void* const* d_in, const int* in_sizes, int n_in,
                              void* d_out, int out_size)
{
    const float* x = nullptr;
    const float* Wm[4] = {nullptr, nullptr, nullptr, nullptr};
    const float* bm[4] = {nullptr, nullptr, nullptr, nullptr};
    int wi = 0, bi = 0;
    for (int i = 0; i < n_in; i++) {
        if (in_sizes[i] == NB * SEQ * HID)      x = (const float*)d_in[i];
        else if (in_sizes[i] == HID * HID) { if (wi < 4) Wm[wi++] = (const float*)d_in[i]; }
        else if (in_sizes[i] == HID)       { if (bi < 4) bm[bi++] = (const float*)d_in[i]; }
    }
    const float* Wq = Wm[0]; const float* Wk = Wm[1];
    const float* Wv = Wm[2]; const float* Wo = Wm[3];
    const float* bq = bm[0]; const float* bk = bm[1];
    const float* bv = bm[2]; const float* bo = bm[3];
    float* out = (float*)d_out;

    const int M = NB * SEQ;  // 4096

    qk_channels_kernel<<<M / 4, 256>>>(x, Wq, Wk, bq, bk);
    {
        dim3 grid(HID / 128, M / 128);
        gemm_mma_kernel<<<grid, 256>>>(x, Wv, bv, nullptr, 0);
    }
    {
        dim3 grid(SEQ / BQ, NHD, NB);
        attn_mma_kernel<<<grid, 256>>>();
    }
    {
        dim3 grid(HID / 128, M / 128);
        gemm_mma_kernel<<<grid, 256>>>(nullptr, Wo, bo, out, 1);
    }
}